// round 12
// baseline (speedup 1.0000x reference)
#include <cuda_runtime.h>
#include <cuda_bf16.h>
#include <cstdint>

typedef __nv_bfloat16 BF;

#define BATCH 8
#define LSEQ  1024
#define DM    256
#define DS    16
#define DC    4
#define DI    512
#define DTR   16
#define BL    (BATCH * LSEQ)   // 8192
#define XDBLC (DTR + 2 * DS)   // 48
#define CH    64
#define NCH   (LSEQ / CH)      // 16

// ---------------- scratch (float units; bf16 arrays carved by cast) --------
static const size_t OFF_XNH   = 0;                                     // bf16 BL*DM
static const size_t OFF_XRH   = OFF_XNH  + (size_t)BL * DM / 2;        // bf16 2*BL*1024
static const size_t OFF_XSCH  = OFF_XRH  + (size_t)2 * BL * 2 * DI / 2;// bf16 2*BL*DI
static const size_t OFF_XDBL  = OFF_XSCH + (size_t)2 * BL * DI / 2;    // f32  2*BL*48
static const size_t OFF_YB    = OFF_XDBL + (size_t)2 * BL * XDBLC;     // bf16 2*BL*DI
static const size_t OFF_WTIN  = OFF_YB   + (size_t)2 * BL * DI / 2;    // bf16 2*1024*256
static const size_t OFF_WTX   = OFF_WTIN + (size_t)2 * 1024 * 256 / 2; // bf16 2*48*512
static const size_t OFF_FWT   = OFF_WTX  + (size_t)2 * 48 * 512 / 2;   // bf16 256*512
static const size_t OFF_OWH   = OFF_FWT  + (size_t)256 * 512 / 2;      // bf16 2*512*256
static const size_t OFF_WCT   = OFF_OWH  + (size_t)2 * 512 * 256 / 2;  // bf16 256*1024
static const size_t OFF_HF    = OFF_WCT  + (size_t)256 * 1024 / 2;     // f32
static const size_t OFF_DS    = OFF_HF   + (size_t)2 * 8 * NCH * 16 * 512;
static const size_t TOTAL_F   = OFF_DS   + (size_t)2 * 8 * NCH * 512;

__device__ float g_buf[TOTAL_F];

// ---------------- fused prep: all weight transforms + LayerNorm ------------
__global__ __launch_bounds__(256)
void prep_kernel(const float* __restrict__ inW0, const float* __restrict__ inW1,
                 const float* __restrict__ xW0,  const float* __restrict__ xW1,
                 const float* __restrict__ fusW,
                 const float* __restrict__ outW0, const float* __restrict__ outW1,
                 BF* __restrict__ WtIn0, BF* __restrict__ WtIn1,
                 BF* __restrict__ WtX0,  BF* __restrict__ WtX1,
                 BF* __restrict__ fusWt, BF* __restrict__ oW0h, BF* __restrict__ oW1h,
                 const float* __restrict__ x, const float* __restrict__ g,
                 const float* __restrict__ bnorm, BF* __restrict__ xn)
{
    __shared__ float tile[32][33];
    int b = blockIdx.x;
    if (b < 960) {
        const float* src; BF* dst; int R, C, tr, t;
        if (b < 256)      { src = inW0;  dst = WtIn0; R = 256; C = 1024; tr = 1; t = b; }
        else if (b < 512) { src = inW1;  dst = WtIn1; R = 256; C = 1024; tr = 1; t = b - 256; }
        else if (b < 544) { src = xW0;   dst = WtX0;  R = 512; C = 48;   tr = 1; t = b - 512; }
        else if (b < 576) { src = xW1;   dst = WtX1;  R = 512; C = 48;   tr = 1; t = b - 544; }
        else if (b < 704) { src = fusW;  dst = fusWt; R = 512; C = 256;  tr = 1; t = b - 576; }
        else if (b < 832) { src = outW0; dst = oW0h;  R = 512; C = 256;  tr = 0; t = b - 704; }
        else              { src = outW1; dst = oW1h;  R = 512; C = 256;  tr = 0; t = b - 832; }
        int ctiles = (C + 31) >> 5;
        int ct = t % ctiles, rt = t / ctiles;
        int c0 = ct * 32, r0 = rt * 32;
        int tx = threadIdx.x & 31, ty = threadIdx.x >> 5;
        if (tr) {
            #pragma unroll
            for (int i = ty; i < 32; i += 8) {
                int r = r0 + i, c = c0 + tx;
                tile[i][tx] = (r < R && c < C) ? src[(size_t)r * C + c] : 0.f;
            }
            __syncthreads();
            #pragma unroll
            for (int i = ty; i < 32; i += 8) {
                int c = c0 + i, r = r0 + tx;
                if (c < C && r < R) dst[(size_t)c * R + r] = __float2bfloat16(tile[tx][i]);
            }
        } else {
            #pragma unroll
            for (int i = ty; i < 32; i += 8) {
                int r = r0 + i, c = c0 + tx;
                if (r < R && c < C)
                    dst[(size_t)r * C + c] = __float2bfloat16(src[(size_t)r * C + c]);
            }
        }
    } else {
        int warp = threadIdx.x >> 5, lane = threadIdx.x & 31;
        int tok = (b - 960) * 8 + warp;
        const float4* xp = (const float4*)(x + (size_t)tok * DM) + lane * 2;
        float4 u0 = xp[0], u1 = xp[1];
        float s  = u0.x + u0.y + u0.z + u0.w + u1.x + u1.y + u1.z + u1.w;
        float s2 = u0.x*u0.x + u0.y*u0.y + u0.z*u0.z + u0.w*u0.w
                 + u1.x*u1.x + u1.y*u1.y + u1.z*u1.z + u1.w*u1.w;
        #pragma unroll
        for (int o = 16; o; o >>= 1) {
            s  += __shfl_xor_sync(0xffffffffu, s,  o);
            s2 += __shfl_xor_sync(0xffffffffu, s2, o);
        }
        float mu  = s * (1.0f / DM);
        float var = s2 * (1.0f / DM) - mu * mu;
        float r = rsqrtf(var + 1e-5f);
        const float4* gp = (const float4*)g + lane * 2;
        const float4* bp = (const float4*)bnorm + lane * 2;
        float4 g0 = gp[0], g1 = gp[1], b0 = bp[0], b1 = bp[1];
        float o_[8];
        o_[0] = (u0.x - mu) * r * g0.x + b0.x;  o_[1] = (u0.y - mu) * r * g0.y + b0.y;
        o_[2] = (u0.z - mu) * r * g0.z + b0.z;  o_[3] = (u0.w - mu) * r * g0.w + b0.w;
        o_[4] = (u1.x - mu) * r * g1.x + b1.x;  o_[5] = (u1.y - mu) * r * g1.y + b1.y;
        o_[6] = (u1.z - mu) * r * g1.z + b1.z;  o_[7] = (u1.w - mu) * r * g1.w + b1.w;
        __nv_bfloat162 h[4];
        #pragma unroll
        for (int i = 0; i < 4; i++) h[i] = __floats2bfloat162_rn(o_[2*i], o_[2*i+1]);
        *(uint4*)(xn + (size_t)tok * DM + lane * 8) = *(uint4*)h;
    }
}

// ---------------- bf16 tensor-core GEMM (64-K tiles) ------------------------
// C[r, coff+c] = sum_k A[amap(r), k] * Bt[c, k]   (both K-major bf16)
// flipMode: 0 none; 1 flip A rows (m^1023) when z==1; 2 dual-A (K split 512).
// epi: 0 f32 store; 2 f32 + bias[c] + resid[r*N+c]; 3 bf16 store.
// K must be a multiple of 64 (all call sites: 256/512/1024).

#define SA 72
#define STAGES 3
#define SMEM_BYTES (STAGES * 2 * 128 * SA * 2)

__device__ __forceinline__ unsigned cvta_s(const void* p) {
    return (unsigned)__cvta_generic_to_shared(p);
}
__device__ __forceinline__ void cp16(unsigned dst, const void* src, int srcbytes) {
    asm volatile("cp.async.cg.shared.global [%0], [%1], 16, %2;\n"
                 :: "r"(dst), "l"(src), "r"(srcbytes));
}

__global__ __launch_bounds__(256, 2)
void mma_gemm(const BF* __restrict__ A0, const BF* __restrict__ A1, int lda, int flipMode,
              const BF* __restrict__ W0, const BF* __restrict__ W1, int ldw,
              float* __restrict__ C0, float* __restrict__ C1, int ldc, int coffz,
              int N, int K, int epi,
              const float* __restrict__ bias0, const float* __restrict__ bias1,
              const float* __restrict__ resid)
{
    extern __shared__ BF smem[];
    BF* As = smem;                            // [STAGES][128][SA]
    BF* Bs = smem + STAGES * 128 * SA;        // [STAGES][128][SA]

    const int z = blockIdx.z;
    const BF* A = z ? A1 : A0;
    const BF* W = z ? W1 : W0;
    float*    C = z ? C1 : C0;
    const float* bias = z ? bias1 : bias0;
    const bool dual = (flipMode == 2);
    const int fA = (flipMode == 1 && z);
    const int coff = coffz * z;

    const int tid = threadIdx.x;
    const int m0 = blockIdx.x * 128;
    const int n0 = blockIdx.y * 128;

    const int ar  = tid >> 1;            // row 0..127
    const int akc = (tid & 1) * 32;      // bf16 col 0 or 32
    int gm = m0 + ar;
    if (fA) gm ^= (LSEQ - 1);
    const BF* A0row = A + (size_t)gm * lda;
    const BF* A1row = dual ? (A1 + (size_t)(gm ^ (LSEQ - 1)) * lda) : A;
    int nr = n0 + ar;
    const BF* Brow = W + (size_t)(nr < N ? nr : 0) * ldw;
    const bool bok = (nr < N);

    const int wid = tid >> 5, lane = tid & 31;
    const int wm = wid & 1, wn = wid >> 1;
    const int lr = lane >> 2, lc = lane & 3;
    const int a_row = (lane & 15);
    const int a_kof = (lane >> 4) * 8;
    const int b_row = (lane & 7) + ((lane & 16) ? 8 : 0);
    const int b_kof = (lane & 8) ? 8 : 0;

    float acc[4][4][4];
    #pragma unroll
    for (int mi = 0; mi < 4; mi++)
        #pragma unroll
        for (int ni = 0; ni < 4; ni++)
            #pragma unroll
            for (int q = 0; q < 4; q++) acc[mi][ni][q] = 0.f;

    const int nk = K >> 6;   // 64-K tiles

    auto loadA = [&](int kk, int buf) {
        BF* dst = As + buf * (128 * SA) + ar * SA + akc;
        #pragma unroll
        for (int j = 0; j < 4; j++) {
            int kg = kk + akc + j * 8;
            const BF* src = (dual && kg >= 512) ? (A1row + kg - 512) : (A0row + kg);
            cp16(cvta_s(dst + j * 8), src, 16);
        }
    };
    auto loadB = [&](int kk, int buf) {
        BF* dst = Bs + buf * (128 * SA) + ar * SA + akc;
        #pragma unroll
        for (int j = 0; j < 4; j++) {
            int kg = kk + akc + j * 8;
            cp16(cvta_s(dst + j * 8), Brow + kg, bok ? 16 : 0);
        }
    };

    loadA(0, 0); loadB(0, 0);
    asm volatile("cp.async.commit_group;\n");
    loadA(64, 1); loadB(64, 1);
    asm volatile("cp.async.commit_group;\n");

    int buf = 0;
    for (int t = 0; t < nk; t++) {
        asm volatile("cp.async.wait_group %0;\n" :: "n"(STAGES - 2));
        __syncthreads();

        if (t + STAGES - 1 < nk) {
            int nb = buf + (STAGES - 1); if (nb >= STAGES) nb -= STAGES;
            loadA((t + STAGES - 1) << 6, nb);
            loadB((t + STAGES - 1) << 6, nb);
        }
        asm volatile("cp.async.commit_group;\n");

        unsigned AsAddr = cvta_s(As + buf * (128 * SA));
        unsigned BsAddr = cvta_s(Bs + buf * (128 * SA));

        #pragma unroll
        for (int s = 0; s < 4; s++) {
            unsigned af[4][4], br[2][4];
            #pragma unroll
            for (int mi = 0; mi < 4; mi++) {
                unsigned a_addr = AsAddr +
                    (unsigned)(((wm * 64 + mi * 16 + a_row) * SA + s * 16 + a_kof) * 2);
                asm volatile(
                    "ldmatrix.sync.aligned.m8n8.x4.shared.b16 {%0,%1,%2,%3}, [%4];\n"
                    : "=r"(af[mi][0]), "=r"(af[mi][1]), "=r"(af[mi][2]), "=r"(af[mi][3])
                    : "r"(a_addr));
            }
            #pragma unroll
            for (int p = 0; p < 2; p++) {
                unsigned b_addr = BsAddr +
                    (unsigned)(((wn * 32 + p * 16 + b_row) * SA + s * 16 + b_kof) * 2);
                asm volatile(
                    "ldmatrix.sync.aligned.m8n8.x4.shared.b16 {%0,%1,%2,%3}, [%4];\n"
                    : "=r"(br[p][0]), "=r"(br[p][1]), "=r"(br[p][2]), "=r"(br[p][3])
                    : "r"(b_addr));
            }
            #pragma unroll
            for (int mi = 0; mi < 4; mi++)
                #pragma unroll
                for (int ni = 0; ni < 4; ni++) {
                    unsigned b0 = br[ni >> 1][(ni & 1) * 2];
                    unsigned b1 = br[ni >> 1][(ni & 1) * 2 + 1];
                    asm volatile(
                        "mma.sync.aligned.m16n8k16.row.col.f32.bf16.bf16.f32 "
                        "{%0,%1,%2,%3},{%4,%5,%6,%7},{%8,%9},{%0,%1,%2,%3};\n"
                        : "+f"(acc[mi][ni][0]), "+f"(acc[mi][ni][1]),
                          "+f"(acc[mi][ni][2]), "+f"(acc[mi][ni][3])
                        : "r"(af[mi][0]), "r"(af[mi][1]), "r"(af[mi][2]), "r"(af[mi][3]),
                          "r"(b0), "r"(b1));
                }
        }
        buf++; if (buf >= STAGES) buf = 0;
    }

    #pragma unroll
    for (int mi = 0; mi < 4; mi++) {
        int r0r = m0 + wm * 64 + mi * 16 + lr;
        #pragma unroll
        for (int ni = 0; ni < 4; ni++) {
            int cb = n0 + wn * 32 + ni * 8 + 2 * lc;
            #pragma unroll
            for (int q = 0; q < 4; q++) {
                int r = r0r + (q >> 1) * 8;
                int c = cb + (q & 1);
                if (c < N) {
                    float v = acc[mi][ni][q];
                    if (epi == 2)
                        v += bias[c] + resid[(size_t)r * N + c];
                    if (epi == 3)
                        ((BF*)C)[(size_t)r * ldc + coff + c] = __float2bfloat16(v);
                    else
                        C[(size_t)r * ldc + coff + c] = v;
                }
            }
        }
    }
}

// ---------------- causal depthwise conv + bias + SiLU (bf16 in/out) --------
__global__ __launch_bounds__(256)
void conv_silu_kernel(const BF* __restrict__ xr0, const BF* __restrict__ xr1,
                      const float* __restrict__ cw0, const float* __restrict__ cw1,
                      const float* __restrict__ cb0, const float* __restrict__ cb1,
                      BF* __restrict__ xh0, BF* __restrict__ xh1)
{
    int dir = blockIdx.y;
    const BF* xr = dir ? xr1 : xr0;
    const float* cw = dir ? cw1 : cw0;
    const float* cb = dir ? cb1 : cb0;
    BF* xh = dir ? xh1 : xh0;

    int idx = blockIdx.x * 256 + threadIdx.x;
    int c   = idx & (DI - 1);
    int rb  = idx >> 9;
    int t0  = rb * 4;
    int tau0 = t0 & (LSEQ - 1);

    const BF* p = xr + (size_t)t0 * (2 * DI) + c;
    float w0 = cw[c * 4 + 0], w1 = cw[c * 4 + 1], w2 = cw[c * 4 + 2], w3 = cw[c * 4 + 3];
    float bias = cb[c];

    float v[7];
    #pragma unroll
    for (int j = 0; j < 7; j++) {
        int off = j - 3;
        bool valid = (tau0 + off >= 0);
        v[j] = valid ? __bfloat162float(p[(long)off * 2 * DI]) : 0.f;
    }
    BF* oh = xh + (size_t)t0 * DI + c;
    #pragma unroll
    for (int k = 0; k < 4; k++) {
        float acc = bias;
        acc = fmaf(v[k],     w0, acc);
        acc = fmaf(v[k + 1], w1, acc);
        acc = fmaf(v[k + 2], w2, acc);
        acc = fmaf(v[k + 3], w3, acc);
        oh[(size_t)k * DI] = __float2bfloat16(acc / (1.f + __expf(-acc)));
    }
}

// ---------------- chunked selective scan (CH=64, NCH=16) --------------------
__device__ __forceinline__ void powers16(float q, float* p) {
    p[0] = q;        p[1] = q * q;     p[2] = p[1] * q;   p[3] = p[1] * p[1];
    p[4] = p[3] * q; p[5] = p[3] * p[1]; p[6] = p[3] * p[2]; p[7] = p[3] * p[3];
    p[8]  = p[7] * q;    p[9]  = p[7] * p[1]; p[10] = p[7] * p[2]; p[11] = p[7] * p[3];
    p[12] = p[7] * p[4]; p[13] = p[7] * p[5]; p[14] = p[7] * p[6]; p[15] = p[7] * p[7];
}

__device__ __forceinline__ bool load_a(const float* __restrict__ ALog, int d, float* a) {
    #pragma unroll
    for (int n = 0; n < 16; n++) a[n] = -__expf(ALog[d * 16 + n]);
    bool fast = true;
    float a1 = a[0];
    #pragma unroll
    for (int n = 1; n < 16; n++)
        fast = fast && (fabsf(a[n] - (n + 1) * a1) <= 1e-4f * fabsf((n + 1) * a1));
    return fast;
}

__device__ __forceinline__ float softplus_f(float v) {
    return (v > 20.f) ? v : log1pf(__expf(v));
}

__global__ __launch_bounds__(128)
void scanA_kernel(const float* __restrict__ xdbl0, const float* __restrict__ xdbl1,
                  const BF* __restrict__ xsc0, const BF* __restrict__ xsc1,
                  const float* __restrict__ dtW0, const float* __restrict__ dtW1,
                  const float* __restrict__ dtB0, const float* __restrict__ dtB1,
                  const float* __restrict__ ALog0, const float* __restrict__ ALog1,
                  BF* __restrict__ y0, BF* __restrict__ y1,
                  float* __restrict__ hfin, float* __restrict__ dSb)
{
    int zb  = blockIdx.z;
    int dir = zb >> 3;
    const float* xdbl = dir ? xdbl1 : xdbl0;
    const BF* xsc     = dir ? xsc1  : xsc0;
    const float* dtW  = dir ? dtW1  : dtW0;
    const float* dtB  = dir ? dtB1  : dtB0;
    const float* ALog = dir ? ALog1 : ALog0;
    BF* y             = dir ? y1    : y0;

    int ch  = blockIdx.y;
    int tid = threadIdx.x;
    int d   = blockIdx.x * 128 + tid;
    int b   = zb & 7;
    int base = b * LSEQ + ch * CH;

    __shared__ float sX[CH][XDBLC];
    for (int i = tid; i < CH * 12; i += 128) {
        int tt = i / 12, q = i % 12;
        *(float4*)&sX[tt][q * 4] =
            *(const float4*)&xdbl[(size_t)(base + tt) * XDBLC + q * 4];
    }
    __syncthreads();

    float wreg[16];
    #pragma unroll
    for (int j = 0; j < 16; j++) wreg[j] = dtW[j * DI + d];
    float dbias = dtB[d];

    float a[16];
    bool fast = load_a(ALog, d, a);
    float a1 = a[0];

    float h[16];
    #pragma unroll
    for (int n = 0; n < 16; n++) h[n] = 0.f;
    float S = 0.f;

    const BF* xp = xsc + (size_t)base * DI + d;
    BF* yp       = y   + (size_t)base * DI + d;

    if (fast) {
        #pragma unroll 2
        for (int t = 0; t < CH; t++) {
            float raw = dbias;
            #pragma unroll
            for (int j = 0; j < 16; j++) raw = fmaf(wreg[j], sX[t][j], raw);
            float dlt = softplus_f(raw);
            float xv  = __bfloat162float(xp[(size_t)t * DI]);
            S += dlt;
            float dx = dlt * xv;
            float p[16];
            powers16(__expf(dlt * a1), p);
            float yv = 0.f;
            #pragma unroll
            for (int n = 0; n < 16; n++) {
                h[n] = fmaf(p[n], h[n], dx * sX[t][16 + n]);
                yv   = fmaf(h[n], sX[t][32 + n], yv);
            }
            yp[(size_t)t * DI] = __float2bfloat16(yv);
        }
    } else {
        for (int t = 0; t < CH; t++) {
            float raw = dbias;
            #pragma unroll
            for (int j = 0; j < 16; j++) raw = fmaf(wreg[j], sX[t][j], raw);
            float dlt = softplus_f(raw);
            float xv  = __bfloat162float(xp[(size_t)t * DI]);
            S += dlt;
            float dx = dlt * xv;
            float yv = 0.f;
            #pragma unroll
            for (int n = 0; n < 16; n++) {
                float dA = __expf(dlt * a[n]);
                h[n] = fmaf(dA, h[n], dx * sX[t][16 + n]);
                yv   = fmaf(h[n], sX[t][32 + n], yv);
            }
            yp[(size_t)t * DI] = __float2bfloat16(yv);
        }
    }

    size_t cc = (size_t)(zb * NCH + ch);
    #pragma unroll
    for (int n = 0; n < 16; n++) hfin[cc * 8192 + n * 512 + d] = h[n];
    dSb[cc * 512 + d] = S;
}

__global__ __launch_bounds__(128)
void scanC_kernel(const float* __restrict__ xdbl0, const float* __restrict__ xdbl1,
                  const BF* __restrict__ xsc0, const BF* __restrict__ xsc1,
                  const BF* __restrict__ xr0, const BF* __restrict__ xr1,
                  const float* __restrict__ dtW0, const float* __restrict__ dtW1,
                  const float* __restrict__ dtB0, const float* __restrict__ dtB1,
                  const float* __restrict__ ALog0, const float* __restrict__ ALog1,
                  const float* __restrict__ Dp0, const float* __restrict__ Dp1,
                  BF* __restrict__ y0, BF* __restrict__ y1,
                  const float* __restrict__ hfin, const float* __restrict__ dSb)
{
    int zb  = blockIdx.z;
    int dir = zb >> 3;
    const float* xdbl = dir ? xdbl1 : xdbl0;
    const BF* xsc     = dir ? xsc1  : xsc0;
    const BF* xr      = dir ? xr1   : xr0;
    const float* dtW  = dir ? dtW1  : dtW0;
    const float* dtB  = dir ? dtB1  : dtB0;
    const float* ALog = dir ? ALog1 : ALog0;
    const float* Dp   = dir ? Dp1   : Dp0;
    BF* y             = dir ? y1    : y0;

    int ch  = blockIdx.y;
    int tid = threadIdx.x;
    int d   = blockIdx.x * 128 + tid;
    int b   = zb & 7;
    int base = b * LSEQ + ch * CH;

    float a[16];
    bool fast = load_a(ALog, d, a);
    float a1 = a[0];
    float Dv = Dp[d];

    const BF* xp = xsc + (size_t)base * DI + d;
    const BF* rp = xr  + (size_t)base * (2 * DI) + DI + d;
    BF* yp       = y   + (size_t)base * DI + d;

    if (ch == 0) {
        #pragma unroll 4
        for (int t = 0; t < CH; t++) {
            float xv  = __bfloat162float(xp[(size_t)t * DI]);
            float res = __bfloat162float(rp[(size_t)t * (2 * DI)]);
            float yl  = __bfloat162float(yp[(size_t)t * DI]);
            float sres = res / (1.f + __expf(-res));
            yp[(size_t)t * DI] = __float2bfloat16((yl + Dv * xv) * sres);
        }
        return;
    }

    __shared__ float sX[CH][XDBLC];
    for (int i = tid; i < CH * 12; i += 128) {
        int tt = i / 12, q = i % 12;
        *(float4*)&sX[tt][q * 4] =
            *(const float4*)&xdbl[(size_t)(base + tt) * XDBLC + q * 4];
    }
    __syncthreads();

    float w[16];
    #pragma unroll
    for (int n = 0; n < 16; n++) w[n] = 0.f;
    for (int c = 0; c < ch; c++) {
        size_t cc = (size_t)(zb * NCH + c);
        float S = dSb[cc * 512 + d];
        float P[16];
        if (fast) {
            powers16(__expf(S * a1), P);
        } else {
            #pragma unroll
            for (int n = 0; n < 16; n++) P[n] = __expf(S * a[n]);
        }
        #pragma unroll
        for (int n = 0; n < 16; n++)
            w[n] = fmaf(P[n], w[n], hfin[cc * 8192 + n * 512 + d]);
    }

    float wreg[16];
    #pragma unroll
    for (int j = 0; j < 16; j++) wreg[j] = dtW[j * DI + d];
    float dbias = dtB[d];

    if (fast) {
        float r = 1.f;
        #pragma unroll 2
        for (int t = 0; t < CH; t++) {
            float raw = dbias;
            #pragma unroll
            for (int j = 0; j < 16; j++) raw = fmaf(wreg[j], sX[t][j], raw);
            float dlt = softplus_f(raw);
            float xv  = __bfloat162float(xp[(size_t)t * DI]);
            float res = __bfloat162float(rp[(size_t)t * (2 * DI)]);
            float yl  = __bfloat162float(yp[(size_t)t * DI]);
            r *= __expf(dlt * a1);
            float p[16];
            powers16(r, p);
            float corr = 0.f;
            #pragma unroll
            for (int n = 0; n < 16; n++)
                corr = fmaf(w[n] * p[n], sX[t][32 + n], corr);
            float sres = res / (1.f + __expf(-res));
            yp[(size_t)t * DI] = __float2bfloat16((yl + corr + Dv * xv) * sres);
        }
    } else {
        float S = 0.f;
        for (int t = 0; t < CH; t++) {
            float raw = dbias;
            #pragma unroll
            for (int j = 0; j < 16; j++) raw = fmaf(wreg[j], sX[t][j], raw);
            float dlt = softplus_f(raw);
            float xv  = __bfloat162float(xp[(size_t)t * DI]);
            float res = __bfloat162float(rp[(size_t)t * (2 * DI)]);
            float yl  = __bfloat162float(yp[(size_t)t * DI]);
            S += dlt;
            float corr = 0.f;
            #pragma unroll
            for (int n = 0; n < 16; n++)
                corr = fmaf(w[n] * __expf(S * a[n]), sX[t][32 + n], corr);
            float sres = res / (1.f + __expf(-res));
            yp[(size_t)t * DI] = __float2bfloat16((yl + corr + Dv * xv) * sres);
        }
    }
}

// ---------------- launcher -------------------------------------------------
extern "C" void kernel_launch(void* const* d_in, const int* in_sizes, int n_in,
                              void* d_out, int out_size)
{
    const float* x      = (const float*)d_in[0];
    const float* norm_g = (const float*)d_in[1];
    const float* norm_b = (const float*)d_in[2];
    const float* inW[2]   = {(const float*)d_in[3],  (const float*)d_in[12]};
    const float* convW[2] = {(const float*)d_in[4],  (const float*)d_in[13]};
    const float* convB[2] = {(const float*)d_in[5],  (const float*)d_in[14]};
    const float* xW[2]    = {(const float*)d_in[6],  (const float*)d_in[15]};
    const float* dtW[2]   = {(const float*)d_in[7],  (const float*)d_in[16]};
    const float* dtB[2]   = {(const float*)d_in[8],  (const float*)d_in[17]};
    const float* ALog[2]  = {(const float*)d_in[9],  (const float*)d_in[18]};
    const float* Dp[2]    = {(const float*)d_in[10], (const float*)d_in[19]};
    const float* outW[2]  = {(const float*)d_in[11], (const float*)d_in[20]};
    const float* fusW = (const float*)d_in[21];
    const float* fusB = (const float*)d_in[22];
    float* out = (float*)d_out;

    float* base = nullptr;
    cudaGetSymbolAddress((void**)&base, g_buf);
    BF*    xn_h      = (BF*)(base + OFF_XNH);
    BF*    xr_[2]    = {(BF*)(base + OFF_XRH),  (BF*)(base + OFF_XRH)  + (size_t)BL * 2 * DI};
    BF*    xsch_[2]  = {(BF*)(base + OFF_XSCH), (BF*)(base + OFF_XSCH) + (size_t)BL * DI};
    float* xdbl_[2]  = {base + OFF_XDBL, base + OFF_XDBL + (size_t)BL * XDBLC};
    BF*    yb_[2]    = {(BF*)(base + OFF_YB),   (BF*)(base + OFF_YB)   + (size_t)BL * DI};
    BF*    WtIn[2]   = {(BF*)(base + OFF_WTIN), (BF*)(base + OFF_WTIN) + (size_t)1024 * 256};
    BF*    WtX[2]    = {(BF*)(base + OFF_WTX),  (BF*)(base + OFF_WTX)  + (size_t)48 * 512};
    BF*    fusWt     = (BF*)(base + OFF_FWT);
    BF*    outWh[2]  = {(BF*)(base + OFF_OWH),  (BF*)(base + OFF_OWH)  + (size_t)512 * 256};
    BF*    WcombT    = (BF*)(base + OFF_WCT);
    float* hfin      = base + OFF_HF;
    float* dSb       = base + OFF_DS;

    static bool attr_set = false;
    if (!attr_set) {
        cudaFuncSetAttribute(mma_gemm, cudaFuncAttributeMaxDynamicSharedMemorySize, SMEM_BYTES);
        attr_set = true;
    }

    // 1) fused prep: weight transforms + LayerNorm
    prep_kernel<<<1984, 256>>>(inW[0], inW[1], xW[0], xW[1], fusW, outW[0], outW[1],
                               WtIn[0], WtIn[1], WtX[0], WtX[1], fusWt, outWh[0], outWh[1],
                               x, norm_g, norm_b, xn_h);

    // 2) WcombT[n, k + z*512] = sum_j fusWt[n, z*256+j] * outWh_z[k, j]
    mma_gemm<<<dim3(2, 4, 2), 256, SMEM_BYTES>>>(
        fusWt, fusWt + 256, 512, 0,
        outWh[0], outWh[1], 256,
        (float*)WcombT, (float*)WcombT, 1024, 512,
        512, 256, 3, nullptr, nullptr, nullptr);

    // 3) in_proj -> bf16 xr, both dirs (flip A rows for backward)
    mma_gemm<<<dim3(BL / 128, 8, 2), 256, SMEM_BYTES>>>(
        xn_h, xn_h, DM, 1,
        WtIn[0], WtIn[1], 256,
        (float*)xr_[0], (float*)xr_[1], 2 * DI, 0,
        2 * DI, DM, 3, nullptr, nullptr, nullptr);

    // 4) causal dw-conv + silu -> bf16 xsc
    conv_silu_kernel<<<dim3((BL / 4) * DI / 256, 2), 256>>>(
        xr_[0], xr_[1], convW[0], convW[1], convB[0], convB[1],
        xsch_[0], xsch_[1]);

    // 5) x_proj -> [dlt | B | C] (f32)
    mma_gemm<<<dim3(BL / 128, 1, 2), 256, SMEM_BYTES>>>(
        xsch_[0], xsch_[1], DI, 0,
        WtX[0], WtX[1], 512,
        xdbl_[0], xdbl_[1], XDBLC, 0,
        XDBLC, 512, 0, nullptr, nullptr, nullptr);

    // 6) chunked scan: local (A) -> combine+correct+gate (C), CH=64
    scanA_kernel<<<dim3(DI / 128, NCH, 16), 128>>>(
        xdbl_[0], xdbl_[1], xsch_[0], xsch_[1],
        dtW[0], dtW[1], dtB[0], dtB[1],
        ALog[0], ALog[1], yb_[0], yb_[1], hfin, dSb);
    scanC_kernel<<<dim3(DI / 128, NCH, 16), 128>>>(
        xdbl_[0], xdbl_[1], xsch_[0], xsch_[1], xr_[0], xr_[1],
        dtW[0], dtW[1], dtB[0], dtB[1],
        ALog[0], ALog[1], Dp[0], Dp[1], yb_[0], yb_[1], hfin, dSb);

    // 7) combined out_proj + fuse + residual (dual-A, K=1024)
    mma_gemm<<<dim3(BL / 128, 2, 1), 256, SMEM_BYTES>>>(
        yb_[0], yb_[1], DI, 2,
        WcombT, WcombT, 1024,
        out, out, DM, 0,
        DM, 1024, 2, fusB, fusB, x);
}

// round 13
// speedup vs baseline: 1.1194x; 1.1194x over previous
#include <cuda_runtime.h>
#include <cuda_bf16.h>
#include <cstdint>

typedef __nv_bfloat16 BF;

#define BATCH 8
#define LSEQ  1024
#define DM    256
#define DS    16
#define DC    4
#define DI    512
#define DTR   16
#define BL    (BATCH * LSEQ)   // 8192
#define XDBLC (DTR + 2 * DS)   // 48
#define CH    64
#define NCH   (LSEQ / CH)      // 16

// ---------------- scratch (float units; bf16 arrays carved by cast) --------
static const size_t OFF_XNH   = 0;                                     // bf16 BL*DM
static const size_t OFF_XRH   = OFF_XNH  + (size_t)BL * DM / 2;        // bf16 2*BL*1024
static const size_t OFF_XSCH  = OFF_XRH  + (size_t)2 * BL * 2 * DI / 2;// bf16 2*BL*DI
static const size_t OFF_XDBL  = OFF_XSCH + (size_t)2 * BL * DI / 2;    // f32  2*BL*48
static const size_t OFF_YB    = OFF_XDBL + (size_t)2 * BL * XDBLC;     // bf16 2*BL*DI
static const size_t OFF_WTIN  = OFF_YB   + (size_t)2 * BL * DI / 2;    // bf16 2*1024*256
static const size_t OFF_WTX   = OFF_WTIN + (size_t)2 * 1024 * 256 / 2; // bf16 2*48*512
static const size_t OFF_FWT   = OFF_WTX  + (size_t)2 * 48 * 512 / 2;   // bf16 256*512
static const size_t OFF_OWH   = OFF_FWT  + (size_t)256 * 512 / 2;      // bf16 2*512*256
static const size_t OFF_WCT   = OFF_OWH  + (size_t)2 * 512 * 256 / 2;  // bf16 256*1024
static const size_t OFF_HF    = OFF_WCT  + (size_t)256 * 1024 / 2;     // f32
static const size_t OFF_DS    = OFF_HF   + (size_t)2 * 8 * NCH * 16 * 512;
static const size_t TOTAL_F   = OFF_DS   + (size_t)2 * 8 * NCH * 512;

__device__ float g_buf[TOTAL_F];

// ---------------- fused prep: all weight transforms + LayerNorm ------------
__global__ __launch_bounds__(256)
void prep_kernel(const float* __restrict__ inW0, const float* __restrict__ inW1,
                 const float* __restrict__ xW0,  const float* __restrict__ xW1,
                 const float* __restrict__ fusW,
                 const float* __restrict__ outW0, const float* __restrict__ outW1,
                 BF* __restrict__ WtIn0, BF* __restrict__ WtIn1,
                 BF* __restrict__ WtX0,  BF* __restrict__ WtX1,
                 BF* __restrict__ fusWt, BF* __restrict__ oW0h, BF* __restrict__ oW1h,
                 const float* __restrict__ x, const float* __restrict__ g,
                 const float* __restrict__ bnorm, BF* __restrict__ xn)
{
    __shared__ float tile[32][33];
    int b = blockIdx.x;
    if (b < 960) {
        const float* src; BF* dst; int R, C, tr, t;
        if (b < 256)      { src = inW0;  dst = WtIn0; R = 256; C = 1024; tr = 1; t = b; }
        else if (b < 512) { src = inW1;  dst = WtIn1; R = 256; C = 1024; tr = 1; t = b - 256; }
        else if (b < 544) { src = xW0;   dst = WtX0;  R = 512; C = 48;   tr = 1; t = b - 512; }
        else if (b < 576) { src = xW1;   dst = WtX1;  R = 512; C = 48;   tr = 1; t = b - 544; }
        else if (b < 704) { src = fusW;  dst = fusWt; R = 512; C = 256;  tr = 1; t = b - 576; }
        else if (b < 832) { src = outW0; dst = oW0h;  R = 512; C = 256;  tr = 0; t = b - 704; }
        else              { src = outW1; dst = oW1h;  R = 512; C = 256;  tr = 0; t = b - 832; }
        int ctiles = (C + 31) >> 5;
        int ct = t % ctiles, rt = t / ctiles;
        int c0 = ct * 32, r0 = rt * 32;
        int tx = threadIdx.x & 31, ty = threadIdx.x >> 5;
        if (tr) {
            #pragma unroll
            for (int i = ty; i < 32; i += 8) {
                int r = r0 + i, c = c0 + tx;
                tile[i][tx] = (r < R && c < C) ? src[(size_t)r * C + c] : 0.f;
            }
            __syncthreads();
            #pragma unroll
            for (int i = ty; i < 32; i += 8) {
                int c = c0 + i, r = r0 + tx;
                if (c < C && r < R) dst[(size_t)c * R + r] = __float2bfloat16(tile[tx][i]);
            }
        } else {
            #pragma unroll
            for (int i = ty; i < 32; i += 8) {
                int r = r0 + i, c = c0 + tx;
                if (r < R && c < C)
                    dst[(size_t)r * C + c] = __float2bfloat16(src[(size_t)r * C + c]);
            }
        }
    } else {
        int warp = threadIdx.x >> 5, lane = threadIdx.x & 31;
        int tok = (b - 960) * 8 + warp;
        const float4* xp = (const float4*)(x + (size_t)tok * DM) + lane * 2;
        float4 u0 = xp[0], u1 = xp[1];
        float s  = u0.x + u0.y + u0.z + u0.w + u1.x + u1.y + u1.z + u1.w;
        float s2 = u0.x*u0.x + u0.y*u0.y + u0.z*u0.z + u0.w*u0.w
                 + u1.x*u1.x + u1.y*u1.y + u1.z*u1.z + u1.w*u1.w;
        #pragma unroll
        for (int o = 16; o; o >>= 1) {
            s  += __shfl_xor_sync(0xffffffffu, s,  o);
            s2 += __shfl_xor_sync(0xffffffffu, s2, o);
        }
        float mu  = s * (1.0f / DM);
        float var = s2 * (1.0f / DM) - mu * mu;
        float r = rsqrtf(var + 1e-5f);
        const float4* gp = (const float4*)g + lane * 2;
        const float4* bp = (const float4*)bnorm + lane * 2;
        float4 g0 = gp[0], g1 = gp[1], b0 = bp[0], b1 = bp[1];
        float o_[8];
        o_[0] = (u0.x - mu) * r * g0.x + b0.x;  o_[1] = (u0.y - mu) * r * g0.y + b0.y;
        o_[2] = (u0.z - mu) * r * g0.z + b0.z;  o_[3] = (u0.w - mu) * r * g0.w + b0.w;
        o_[4] = (u1.x - mu) * r * g1.x + b1.x;  o_[5] = (u1.y - mu) * r * g1.y + b1.y;
        o_[6] = (u1.z - mu) * r * g1.z + b1.z;  o_[7] = (u1.w - mu) * r * g1.w + b1.w;
        __nv_bfloat162 h[4];
        #pragma unroll
        for (int i = 0; i < 4; i++) h[i] = __floats2bfloat162_rn(o_[2*i], o_[2*i+1]);
        *(uint4*)(xn + (size_t)tok * DM + lane * 8) = *(uint4*)h;
    }
}

// ---------------- bf16 tensor-core GEMM (32-K tiles, proven config) ---------
// z = blockIdx.z + zoff selects direction / pointer set.
#define SA 40
#define STAGES 3
#define SMEM_BYTES (STAGES * 2 * 128 * SA * 2)

__device__ __forceinline__ unsigned cvta_s(const void* p) {
    return (unsigned)__cvta_generic_to_shared(p);
}
__device__ __forceinline__ void cp16(unsigned dst, const void* src, int srcbytes) {
    asm volatile("cp.async.cg.shared.global [%0], [%1], 16, %2;\n"
                 :: "r"(dst), "l"(src), "r"(srcbytes));
}

__global__ __launch_bounds__(256, 2)
void mma_gemm(const BF* __restrict__ A0, const BF* __restrict__ A1, int lda, int flipMode,
              const BF* __restrict__ W0, const BF* __restrict__ W1, int ldw,
              float* __restrict__ C0, float* __restrict__ C1, int ldc, int coffz,
              int N, int K, int epi,
              const float* __restrict__ bias0, const float* __restrict__ bias1,
              const float* __restrict__ resid, int zoff)
{
    extern __shared__ BF smem[];
    BF* As = smem;
    BF* Bs = smem + STAGES * 128 * SA;

    const int z = blockIdx.z + zoff;
    const BF* A = z ? A1 : A0;
    const BF* W = z ? W1 : W0;
    float*    C = z ? C1 : C0;
    const float* bias = z ? bias1 : bias0;
    const bool dual = (flipMode == 2);
    const int fA = (flipMode == 1 && z);
    const int coff = coffz * z;

    const int tid = threadIdx.x;
    const int m0 = blockIdx.x * 128;
    const int n0 = blockIdx.y * 128;

    const int ar  = tid >> 1;
    const int akc = (tid & 1) * 16;
    int gm = m0 + ar;
    if (fA) gm ^= (LSEQ - 1);
    const BF* A0row = A + (size_t)gm * lda;
    const BF* A1row = dual ? (A1 + (size_t)(gm ^ (LSEQ - 1)) * lda) : A;
    int nr = n0 + ar;
    const BF* Brow = W + (size_t)(nr < N ? nr : 0) * ldw;
    const bool bok = (nr < N);

    const int wid = tid >> 5, lane = tid & 31;
    const int wm = wid & 1, wn = wid >> 1;
    const int lr = lane >> 2, lc = lane & 3;
    const int a_row = (lane & 15);
    const int a_kof = (lane >> 4) * 8;
    const int b_row = (lane & 7) + ((lane & 16) ? 8 : 0);
    const int b_kof = (lane & 8) ? 8 : 0;

    float acc[4][4][4];
    #pragma unroll
    for (int mi = 0; mi < 4; mi++)
        #pragma unroll
        for (int ni = 0; ni < 4; ni++)
            #pragma unroll
            for (int q = 0; q < 4; q++) acc[mi][ni][q] = 0.f;

    const int nk = K >> 5;

    auto loadA = [&](int kk, int buf) {
        BF* dst = As + buf * (128 * SA) + ar * SA + akc;
        #pragma unroll
        for (int j = 0; j < 2; j++) {
            int kg = kk + akc + j * 8;
            const BF* src = (dual && kg >= 512) ? (A1row + kg - 512) : (A0row + kg);
            cp16(cvta_s(dst + j * 8), src, 16);
        }
    };
    auto loadB = [&](int kk, int buf) {
        BF* dst = Bs + buf * (128 * SA) + ar * SA + akc;
        #pragma unroll
        for (int j = 0; j < 2; j++) {
            int kg = kk + akc + j * 8;
            cp16(cvta_s(dst + j * 8), Brow + kg, bok ? 16 : 0);
        }
    };

    loadA(0, 0); loadB(0, 0);
    asm volatile("cp.async.commit_group;\n");
    loadA(32, 1); loadB(32, 1);
    asm volatile("cp.async.commit_group;\n");

    int buf = 0;
    for (int t = 0; t < nk; t++) {
        asm volatile("cp.async.wait_group %0;\n" :: "n"(STAGES - 2));
        __syncthreads();

        if (t + STAGES - 1 < nk) {
            int nb = buf + (STAGES - 1); if (nb >= STAGES) nb -= STAGES;
            loadA((t + STAGES - 1) << 5, nb);
            loadB((t + STAGES - 1) << 5, nb);
        }
        asm volatile("cp.async.commit_group;\n");

        unsigned AsAddr = cvta_s(As + buf * (128 * SA));
        unsigned BsAddr = cvta_s(Bs + buf * (128 * SA));

        #pragma unroll
        for (int s = 0; s < 2; s++) {
            unsigned af[4][4], br[2][4];
            #pragma unroll
            for (int mi = 0; mi < 4; mi++) {
                unsigned a_addr = AsAddr +
                    (unsigned)(((wm * 64 + mi * 16 + a_row) * SA + s * 16 + a_kof) * 2);
                asm volatile(
                    "ldmatrix.sync.aligned.m8n8.x4.shared.b16 {%0,%1,%2,%3}, [%4];\n"
                    : "=r"(af[mi][0]), "=r"(af[mi][1]), "=r"(af[mi][2]), "=r"(af[mi][3])
                    : "r"(a_addr));
            }
            #pragma unroll
            for (int p = 0; p < 2; p++) {
                unsigned b_addr = BsAddr +
                    (unsigned)(((wn * 32 + p * 16 + b_row) * SA + s * 16 + b_kof) * 2);
                asm volatile(
                    "ldmatrix.sync.aligned.m8n8.x4.shared.b16 {%0,%1,%2,%3}, [%4];\n"
                    : "=r"(br[p][0]), "=r"(br[p][1]), "=r"(br[p][2]), "=r"(br[p][3])
                    : "r"(b_addr));
            }
            #pragma unroll
            for (int mi = 0; mi < 4; mi++)
                #pragma unroll
                for (int ni = 0; ni < 4; ni++) {
                    unsigned b0 = br[ni >> 1][(ni & 1) * 2];
                    unsigned b1 = br[ni >> 1][(ni & 1) * 2 + 1];
                    asm volatile(
                        "mma.sync.aligned.m16n8k16.row.col.f32.bf16.bf16.f32 "
                        "{%0,%1,%2,%3},{%4,%5,%6,%7},{%8,%9},{%0,%1,%2,%3};\n"
                        : "+f"(acc[mi][ni][0]), "+f"(acc[mi][ni][1]),
                          "+f"(acc[mi][ni][2]), "+f"(acc[mi][ni][3])
                        : "r"(af[mi][0]), "r"(af[mi][1]), "r"(af[mi][2]), "r"(af[mi][3]),
                          "r"(b0), "r"(b1));
                }
        }
        buf++; if (buf >= STAGES) buf = 0;
    }

    #pragma unroll
    for (int mi = 0; mi < 4; mi++) {
        int r0r = m0 + wm * 64 + mi * 16 + lr;
        #pragma unroll
        for (int ni = 0; ni < 4; ni++) {
            int cb = n0 + wn * 32 + ni * 8 + 2 * lc;
            #pragma unroll
            for (int q = 0; q < 4; q++) {
                int r = r0r + (q >> 1) * 8;
                int c = cb + (q & 1);
                if (c < N) {
                    float v = acc[mi][ni][q];
                    if (epi == 2)
                        v += bias[c] + resid[(size_t)r * N + c];
                    if (epi == 3)
                        ((BF*)C)[(size_t)r * ldc + coff + c] = __float2bfloat16(v);
                    else
                        C[(size_t)r * ldc + coff + c] = v;
                }
            }
        }
    }
}

// ---------------- causal depthwise conv + bias + SiLU (per-dir) -------------
__global__ __launch_bounds__(256)
void conv_silu_kernel(const BF* __restrict__ xr0, const BF* __restrict__ xr1,
                      const float* __restrict__ cw0, const float* __restrict__ cw1,
                      const float* __restrict__ cb0, const float* __restrict__ cb1,
                      BF* __restrict__ xh0, BF* __restrict__ xh1, int dir)
{
    const BF* xr = dir ? xr1 : xr0;
    const float* cw = dir ? cw1 : cw0;
    const float* cb = dir ? cb1 : cb0;
    BF* xh = dir ? xh1 : xh0;

    int idx = blockIdx.x * 256 + threadIdx.x;
    int c   = idx & (DI - 1);
    int rb  = idx >> 9;
    int t0  = rb * 4;
    int tau0 = t0 & (LSEQ - 1);

    const BF* p = xr + (size_t)t0 * (2 * DI) + c;
    float w0 = cw[c * 4 + 0], w1 = cw[c * 4 + 1], w2 = cw[c * 4 + 2], w3 = cw[c * 4 + 3];
    float bias = cb[c];

    float v[7];
    #pragma unroll
    for (int j = 0; j < 7; j++) {
        int off = j - 3;
        bool valid = (tau0 + off >= 0);
        v[j] = valid ? __bfloat162float(p[(long)off * 2 * DI]) : 0.f;
    }
    BF* oh = xh + (size_t)t0 * DI + c;
    #pragma unroll
    for (int k = 0; k < 4; k++) {
        float acc = bias;
        acc = fmaf(v[k],     w0, acc);
        acc = fmaf(v[k + 1], w1, acc);
        acc = fmaf(v[k + 2], w2, acc);
        acc = fmaf(v[k + 3], w3, acc);
        oh[(size_t)k * DI] = __float2bfloat16(acc / (1.f + __expf(-acc)));
    }
}

// ---------------- chunked selective scan (CH=64, per-dir via zoff) ----------
__device__ __forceinline__ void powers16(float q, float* p) {
    p[0] = q;        p[1] = q * q;     p[2] = p[1] * q;   p[3] = p[1] * p[1];
    p[4] = p[3] * q; p[5] = p[3] * p[1]; p[6] = p[3] * p[2]; p[7] = p[3] * p[3];
    p[8]  = p[7] * q;    p[9]  = p[7] * p[1]; p[10] = p[7] * p[2]; p[11] = p[7] * p[3];
    p[12] = p[7] * p[4]; p[13] = p[7] * p[5]; p[14] = p[7] * p[6]; p[15] = p[7] * p[7];
}

__device__ __forceinline__ bool load_a(const float* __restrict__ ALog, int d, float* a) {
    #pragma unroll
    for (int n = 0; n < 16; n++) a[n] = -__expf(ALog[d * 16 + n]);
    bool fast = true;
    float a1 = a[0];
    #pragma unroll
    for (int n = 1; n < 16; n++)
        fast = fast && (fabsf(a[n] - (n + 1) * a1) <= 1e-4f * fabsf((n + 1) * a1));
    return fast;
}

__device__ __forceinline__ float softplus_f(float v) {
    return (v > 20.f) ? v : log1pf(__expf(v));
}

__global__ __launch_bounds__(128)
void scanA_kernel(const float* __restrict__ xdbl0, const float* __restrict__ xdbl1,
                  const BF* __restrict__ xsc0, const BF* __restrict__ xsc1,
                  const float* __restrict__ dtW0, const float* __restrict__ dtW1,
                  const float* __restrict__ dtB0, const float* __restrict__ dtB1,
                  const float* __restrict__ ALog0, const float* __restrict__ ALog1,
                  BF* __restrict__ y0, BF* __restrict__ y1,
                  float* __restrict__ hfin, float* __restrict__ dSb, int zoff)
{
    int zb  = blockIdx.z + zoff;
    int dir = zb >> 3;
    const float* xdbl = dir ? xdbl1 : xdbl0;
    const BF* xsc     = dir ? xsc1  : xsc0;
    const float* dtW  = dir ? dtW1  : dtW0;
    const float* dtB  = dir ? dtB1  : dtB0;
    const float* ALog = dir ? ALog1 : ALog0;
    BF* y             = dir ? y1    : y0;

    int ch  = blockIdx.y;
    int tid = threadIdx.x;
    int d   = blockIdx.x * 128 + tid;
    int b   = zb & 7;
    int base = b * LSEQ + ch * CH;

    __shared__ float sX[CH][XDBLC];
    for (int i = tid; i < CH * 12; i += 128) {
        int tt = i / 12, q = i % 12;
        *(float4*)&sX[tt][q * 4] =
            *(const float4*)&xdbl[(size_t)(base + tt) * XDBLC + q * 4];
    }
    __syncthreads();

    float wreg[16];
    #pragma unroll
    for (int j = 0; j < 16; j++) wreg[j] = dtW[j * DI + d];
    float dbias = dtB[d];

    float a[16];
    bool fast = load_a(ALog, d, a);
    float a1 = a[0];

    float h[16];
    #pragma unroll
    for (int n = 0; n < 16; n++) h[n] = 0.f;
    float S = 0.f;

    const BF* xp = xsc + (size_t)base * DI + d;
    BF* yp       = y   + (size_t)base * DI + d;

    if (fast) {
        #pragma unroll 2
        for (int t = 0; t < CH; t++) {
            float raw = dbias;
            #pragma unroll
            for (int j = 0; j < 16; j++) raw = fmaf(wreg[j], sX[t][j], raw);
            float dlt = softplus_f(raw);
            float xv  = __bfloat162float(xp[(size_t)t * DI]);
            S += dlt;
            float dx = dlt * xv;
            float p[16];
            powers16(__expf(dlt * a1), p);
            float yv = 0.f;
            #pragma unroll
            for (int n = 0; n < 16; n++) {
                h[n] = fmaf(p[n], h[n], dx * sX[t][16 + n]);
                yv   = fmaf(h[n], sX[t][32 + n], yv);
            }
            yp[(size_t)t * DI] = __float2bfloat16(yv);
        }
    } else {
        for (int t = 0; t < CH; t++) {
            float raw = dbias;
            #pragma unroll
            for (int j = 0; j < 16; j++) raw = fmaf(wreg[j], sX[t][j], raw);
            float dlt = softplus_f(raw);
            float xv  = __bfloat162float(xp[(size_t)t * DI]);
            S += dlt;
            float dx = dlt * xv;
            float yv = 0.f;
            #pragma unroll
            for (int n = 0; n < 16; n++) {
                float dA = __expf(dlt * a[n]);
                h[n] = fmaf(dA, h[n], dx * sX[t][16 + n]);
                yv   = fmaf(h[n], sX[t][32 + n], yv);
            }
            yp[(size_t)t * DI] = __float2bfloat16(yv);
        }
    }

    size_t cc = (size_t)(zb * NCH + ch);
    #pragma unroll
    for (int n = 0; n < 16; n++) hfin[cc * 8192 + n * 512 + d] = h[n];
    dSb[cc * 512 + d] = S;
}

__global__ __launch_bounds__(128)
void scanC_kernel(const float* __restrict__ xdbl0, const float* __restrict__ xdbl1,
                  const BF* __restrict__ xsc0, const BF* __restrict__ xsc1,
                  const BF* __restrict__ xr0, const BF* __restrict__ xr1,
                  const float* __restrict__ dtW0, const float* __restrict__ dtW1,
                  const float* __restrict__ dtB0, const float* __restrict__ dtB1,
                  const float* __restrict__ ALog0, const float* __restrict__ ALog1,
                  const float* __restrict__ Dp0, const float* __restrict__ Dp1,
                  BF* __restrict__ y0, BF* __restrict__ y1,
                  const float* __restrict__ hfin, const float* __restrict__ dSb, int zoff)
{
    int zb  = blockIdx.z + zoff;
    int dir = zb >> 3;
    const float* xdbl = dir ? xdbl1 : xdbl0;
    const BF* xsc     = dir ? xsc1  : xsc0;
    const BF* xr      = dir ? xr1   : xr0;
    const float* dtW  = dir ? dtW1  : dtW0;
    const float* dtB  = dir ? dtB1  : dtB0;
    const float* ALog = dir ? ALog1 : ALog0;
    const float* Dp   = dir ? Dp1   : Dp0;
    BF* y             = dir ? y1    : y0;

    int ch  = blockIdx.y;
    int tid = threadIdx.x;
    int d   = blockIdx.x * 128 + tid;
    int b   = zb & 7;
    int base = b * LSEQ + ch * CH;

    float a[16];
    bool fast = load_a(ALog, d, a);
    float a1 = a[0];
    float Dv = Dp[d];

    const BF* xp = xsc + (size_t)base * DI + d;
    const BF* rp = xr  + (size_t)base * (2 * DI) + DI + d;
    BF* yp       = y   + (size_t)base * DI + d;

    if (ch == 0) {
        #pragma unroll 4
        for (int t = 0; t < CH; t++) {
            float xv  = __bfloat162float(xp[(size_t)t * DI]);
            float res = __bfloat162float(rp[(size_t)t * (2 * DI)]);
            float yl  = __bfloat162float(yp[(size_t)t * DI]);
            float sres = res / (1.f + __expf(-res));
            yp[(size_t)t * DI] = __float2bfloat16((yl + Dv * xv) * sres);
        }
        return;
    }

    __shared__ float sX[CH][XDBLC];
    for (int i = tid; i < CH * 12; i += 128) {
        int tt = i / 12, q = i % 12;
        *(float4*)&sX[tt][q * 4] =
            *(const float4*)&xdbl[(size_t)(base + tt) * XDBLC + q * 4];
    }
    __syncthreads();

    float w[16];
    #pragma unroll
    for (int n = 0; n < 16; n++) w[n] = 0.f;
    for (int c = 0; c < ch; c++) {
        size_t cc = (size_t)(zb * NCH + c);
        float S = dSb[cc * 512 + d];
        float P[16];
        if (fast) {
            powers16(__expf(S * a1), P);
        } else {
            #pragma unroll
            for (int n = 0; n < 16; n++) P[n] = __expf(S * a[n]);
        }
        #pragma unroll
        for (int n = 0; n < 16; n++)
            w[n] = fmaf(P[n], w[n], hfin[cc * 8192 + n * 512 + d]);
    }

    float wreg[16];
    #pragma unroll
    for (int j = 0; j < 16; j++) wreg[j] = dtW[j * DI + d];
    float dbias = dtB[d];

    if (fast) {
        float r = 1.f;
        #pragma unroll 2
        for (int t = 0; t < CH; t++) {
            float raw = dbias;
            #pragma unroll
            for (int j = 0; j < 16; j++) raw = fmaf(wreg[j], sX[t][j], raw);
            float dlt = softplus_f(raw);
            float xv  = __bfloat162float(xp[(size_t)t * DI]);
            float res = __bfloat162float(rp[(size_t)t * (2 * DI)]);
            float yl  = __bfloat162float(yp[(size_t)t * DI]);
            r *= __expf(dlt * a1);
            float p[16];
            powers16(r, p);
            float corr = 0.f;
            #pragma unroll
            for (int n = 0; n < 16; n++)
                corr = fmaf(w[n] * p[n], sX[t][32 + n], corr);
            float sres = res / (1.f + __expf(-res));
            yp[(size_t)t * DI] = __float2bfloat16((yl + corr + Dv * xv) * sres);
        }
    } else {
        float S = 0.f;
        for (int t = 0; t < CH; t++) {
            float raw = dbias;
            #pragma unroll
            for (int j = 0; j < 16; j++) raw = fmaf(wreg[j], sX[t][j], raw);
            float dlt = softplus_f(raw);
            float xv  = __bfloat162float(xp[(size_t)t * DI]);
            float res = __bfloat162float(rp[(size_t)t * (2 * DI)]);
            float yl  = __bfloat162float(yp[(size_t)t * DI]);
            S += dlt;
            float corr = 0.f;
            #pragma unroll
            for (int n = 0; n < 16; n++)
                corr = fmaf(w[n] * __expf(S * a[n]), sX[t][32 + n], corr);
            float sres = res / (1.f + __expf(-res));
            yp[(size_t)t * DI] = __float2bfloat16((yl + corr + Dv * xv) * sres);
        }
    }
}

// ---------------- launcher: two-stream direction pipeline -------------------
extern "C" void kernel_launch(void* const* d_in, const int* in_sizes, int n_in,
                              void* d_out, int out_size)
{
    const float* x      = (const float*)d_in[0];
    const float* norm_g = (const float*)d_in[1];
    const float* norm_b = (const float*)d_in[2];
    const float* inW[2]   = {(const float*)d_in[3],  (const float*)d_in[12]};
    const float* convW[2] = {(const float*)d_in[4],  (const float*)d_in[13]};
    const float* convB[2] = {(const float*)d_in[5],  (const float*)d_in[14]};
    const float* xW[2]    = {(const float*)d_in[6],  (const float*)d_in[15]};
    const float* dtW[2]   = {(const float*)d_in[7],  (const float*)d_in[16]};
    const float* dtB[2]   = {(const float*)d_in[8],  (const float*)d_in[17]};
    const float* ALog[2]  = {(const float*)d_in[9],  (const float*)d_in[18]};
    const float* Dp[2]    = {(const float*)d_in[10], (const float*)d_in[19]};
    const float* outW[2]  = {(const float*)d_in[11], (const float*)d_in[20]};
    const float* fusW = (const float*)d_in[21];
    const float* fusB = (const float*)d_in[22];
    float* out = (float*)d_out;

    float* base = nullptr;
    cudaGetSymbolAddress((void**)&base, g_buf);
    BF*    xn_h      = (BF*)(base + OFF_XNH);
    BF*    xr_[2]    = {(BF*)(base + OFF_XRH),  (BF*)(base + OFF_XRH)  + (size_t)BL * 2 * DI};
    BF*    xsch_[2]  = {(BF*)(base + OFF_XSCH), (BF*)(base + OFF_XSCH) + (size_t)BL * DI};
    float* xdbl_[2]  = {base + OFF_XDBL, base + OFF_XDBL + (size_t)BL * XDBLC};
    BF*    yb_[2]    = {(BF*)(base + OFF_YB),   (BF*)(base + OFF_YB)   + (size_t)BL * DI};
    BF*    WtIn[2]   = {(BF*)(base + OFF_WTIN), (BF*)(base + OFF_WTIN) + (size_t)1024 * 256};
    BF*    WtX[2]    = {(BF*)(base + OFF_WTX),  (BF*)(base + OFF_WTX)  + (size_t)48 * 512};
    BF*    fusWt     = (BF*)(base + OFF_FWT);
    BF*    outWh[2]  = {(BF*)(base + OFF_OWH),  (BF*)(base + OFF_OWH)  + (size_t)512 * 256};
    BF*    WcombT    = (BF*)(base + OFF_WCT);
    float* hfin      = base + OFF_HF;
    float* dSb       = base + OFF_DS;

    static bool inited = false;
    static cudaStream_t s1;
    static cudaEvent_t evFork, evJoin;
    if (!inited) {
        cudaFuncSetAttribute(mma_gemm, cudaFuncAttributeMaxDynamicSharedMemorySize, SMEM_BYTES);
        cudaStreamCreateWithFlags(&s1, cudaStreamNonBlocking);
        cudaEventCreateWithFlags(&evFork, cudaEventDisableTiming);
        cudaEventCreateWithFlags(&evJoin, cudaEventDisableTiming);
        inited = true;
    }

    // 1) fused prep (default stream)
    prep_kernel<<<1984, 256>>>(inW[0], inW[1], xW[0], xW[1], fusW, outW[0], outW[1],
                               WtIn[0], WtIn[1], WtX[0], WtX[1], fusWt, outWh[0], outWh[1],
                               x, norm_g, norm_b, xn_h);

    // fork: s1 runs Wcomb + the ENTIRE dir-1 chain
    cudaEventRecord(evFork, 0);
    cudaStreamWaitEvent(s1, evFork, 0);

    // ---- s1: Wcomb (both halves) ----
    mma_gemm<<<dim3(2, 4, 2), 256, SMEM_BYTES, s1>>>(
        fusWt, fusWt + 256, 512, 0,
        outWh[0], outWh[1], 256,
        (float*)WcombT, (float*)WcombT, 1024, 512,
        512, 256, 3, nullptr, nullptr, nullptr, 0);

    // ---- per-direction chains ----
    for (int dir = 0; dir < 2; dir++) {
        cudaStream_t st = dir ? s1 : (cudaStream_t)0;
        // in_proj (z = dir)
        mma_gemm<<<dim3(BL / 128, 8, 1), 256, SMEM_BYTES, st>>>(
            xn_h, xn_h, DM, 1,
            WtIn[0], WtIn[1], 256,
            (float*)xr_[0], (float*)xr_[1], 2 * DI, 0,
            2 * DI, DM, 3, nullptr, nullptr, nullptr, dir);
        // conv
        conv_silu_kernel<<<dim3((BL / 4) * DI / 256, 1), 256, 0, st>>>(
            xr_[0], xr_[1], convW[0], convW[1], convB[0], convB[1],
            xsch_[0], xsch_[1], dir);
        // x_proj
        mma_gemm<<<dim3(BL / 128, 1, 1), 256, SMEM_BYTES, st>>>(
            xsch_[0], xsch_[1], DI, 0,
            WtX[0], WtX[1], 512,
            xdbl_[0], xdbl_[1], XDBLC, 0,
            XDBLC, 512, 0, nullptr, nullptr, nullptr, dir);
        // scanA + scanC (zoff = dir*8)
        scanA_kernel<<<dim3(DI / 128, NCH, 8), 128, 0, st>>>(
            xdbl_[0], xdbl_[1], xsch_[0], xsch_[1],
            dtW[0], dtW[1], dtB[0], dtB[1],
            ALog[0], ALog[1], yb_[0], yb_[1], hfin, dSb, dir * 8);
        scanC_kernel<<<dim3(DI / 128, NCH, 8), 128, 0, st>>>(
            xdbl_[0], xdbl_[1], xsch_[0], xsch_[1], xr_[0], xr_[1],
            dtW[0], dtW[1], dtB[0], dtB[1],
            ALog[0], ALog[1], Dp[0], Dp[1], yb_[0], yb_[1], hfin, dSb, dir * 8);
    }

    // join: default stream waits for s1 (dir-1 chain + Wcomb)
    cudaEventRecord(evJoin, s1);
    cudaStreamWaitEvent((cudaStream_t)0, evJoin, 0);

    // 7) combined out_proj + fuse + residual (dual-A, K=1024) on default
    mma_gemm<<<dim3(BL / 128, 2, 1), 256, SMEM_BYTES>>>(
        yb_[0], yb_[1], DI, 2,
        WcombT, WcombT, 1024,
        out, out, DM, 0,
        DM, 1024, 2, fusB, fusB, x, 0);
}